// round 7
// baseline (speedup 1.0000x reference)
#include <cuda_runtime.h>
#include <cuda_bf16.h>
#include <cstdint>

#define SS 4
#define NN 4096
#define DD 64
#define TM 64     // i rows per CTA
#define TN 256    // j rows per CTA

// Pre-split bf16 hi/lo operand arrays (2 MB each, static — no allocs allowed)
__device__ __nv_bfloat16 g_Ah[(size_t)SS * NN * DD];
__device__ __nv_bfloat16 g_Al[(size_t)SS * NN * DD];
__device__ __nv_bfloat16 g_Bh[(size_t)SS * NN * DD];
__device__ __nv_bfloat16 g_Bl[(size_t)SS * NN * DD];

__device__ __forceinline__ uint32_t pkbf2(float a, float b) {
    __nv_bfloat162 t = __floats2bfloat162_rn(a, b);
    return *(uint32_t*)&t;
}

// ---------------------------------------------------------------------------
// Stage 1 (fused): blocks [0,128):  Q = x0 @ W^T, split -> g_Bh/g_Bl
//                  blocks [128,192): split x1 -> g_Ah/g_Al
// ---------------------------------------------------------------------------
__global__ __launch_bounds__(256) void prep_kernel(const float* __restrict__ x0,
                                                   const float* __restrict__ x1,
                                                   const float* __restrict__ W) {
    const int tid = threadIdx.x;
    if (blockIdx.x < 128) {
        __shared__ float Ws[DD * DD];
        #pragma unroll
        for (int i = tid; i < DD * DD / 4; i += 256)
            ((float4*)Ws)[i] = ((const float4*)W)[i];
        __syncthreads();

        int gid = blockIdx.x * 256 + tid;      // 0 .. 2*S*N-1
        int row = gid >> 1;
        int half = gid & 1;                    // 32 d-outputs

        const float4* xr = (const float4*)(x0 + (size_t)row * DD);
        float4 x[16];
        #pragma unroll
        for (int e = 0; e < 16; ++e) x[e] = xr[e];

        uint2* qh = (uint2*)(g_Bh + (size_t)row * DD + half * 32);
        uint2* ql = (uint2*)(g_Bl + (size_t)row * DD + half * 32);
        #pragma unroll
        for (int d4 = 0; d4 < 8; ++d4) {
            float r[4];
            #pragma unroll
            for (int dd = 0; dd < 4; ++dd) {
                int d = half * 32 + d4 * 4 + dd;
                const float4* wr = (const float4*)(Ws + d * DD);
                float a0 = 0.f, a1 = 0.f, a2 = 0.f, a3 = 0.f;
                #pragma unroll
                for (int e4 = 0; e4 < 16; e4 += 4) {
                    float4 w0 = wr[e4 + 0], w1 = wr[e4 + 1], w2 = wr[e4 + 2], w3 = wr[e4 + 3];
                    a0 += x[e4 + 0].x * w0.x + x[e4 + 0].y * w0.y + x[e4 + 0].z * w0.z + x[e4 + 0].w * w0.w;
                    a1 += x[e4 + 1].x * w1.x + x[e4 + 1].y * w1.y + x[e4 + 1].z * w1.z + x[e4 + 1].w * w1.w;
                    a2 += x[e4 + 2].x * w2.x + x[e4 + 2].y * w2.y + x[e4 + 2].z * w2.z + x[e4 + 2].w * w2.w;
                    a3 += x[e4 + 3].x * w3.x + x[e4 + 3].y * w3.y + x[e4 + 3].z * w3.z + x[e4 + 3].w * w3.w;
                }
                r[dd] = (a0 + a1) + (a2 + a3);
            }
            float h0 = __bfloat162float(__float2bfloat16(r[0]));
            float h1 = __bfloat162float(__float2bfloat16(r[1]));
            float h2 = __bfloat162float(__float2bfloat16(r[2]));
            float h3 = __bfloat162float(__float2bfloat16(r[3]));
            qh[d4] = make_uint2(pkbf2(h0, h1), pkbf2(h2, h3));
            ql[d4] = make_uint2(pkbf2(r[0] - h0, r[1] - h1), pkbf2(r[2] - h2, r[3] - h3));
        }
    } else {
        // x1 split: 64 blocks over 262144 float4
        int idx = (blockIdx.x - 128) * 256 + tid;
        const float4* src = (const float4*)x1;
        uint2* ah = (uint2*)g_Ah;
        uint2* al = (uint2*)g_Al;
        #pragma unroll
        for (int it = 0; it < 16; ++it) {
            int i = it * 16384 + idx;
            float4 v = src[i];
            float hx = __bfloat162float(__float2bfloat16(v.x));
            float hy = __bfloat162float(__float2bfloat16(v.y));
            float hz = __bfloat162float(__float2bfloat16(v.z));
            float hw = __bfloat162float(__float2bfloat16(v.w));
            ah[i] = make_uint2(pkbf2(hx, hy), pkbf2(hz, hw));
            al[i] = make_uint2(pkbf2(v.x - hx, v.y - hy), pkbf2(v.z - hz, v.w - hw));
        }
    }
}

// ---------------------------------------------------------------------------
// Baseline-PTX tensor core helpers
// ---------------------------------------------------------------------------
__device__ __forceinline__ uint32_t smem_u32(const void* p) {
    uint32_t a;
    asm("{ .reg .u64 t; cvta.to.shared.u64 t, %1; cvt.u32.u64 %0, t; }" : "=r"(a) : "l"(p));
    return a;
}

__device__ __forceinline__ void ldsm4(uint32_t* r, uint32_t addr) {
    asm volatile("ldmatrix.sync.aligned.m8n8.x4.shared.b16 {%0,%1,%2,%3}, [%4];"
                 : "=r"(r[0]), "=r"(r[1]), "=r"(r[2]), "=r"(r[3]) : "r"(addr));
}

__device__ __forceinline__ void mma16816(float* c, const uint32_t* a,
                                         const uint32_t* b) {
    asm volatile(
        "mma.sync.aligned.m16n8k16.row.col.f32.bf16.bf16.f32 "
        "{%0,%1,%2,%3}, {%4,%5,%6,%7}, {%8,%9}, {%0,%1,%2,%3};"
        : "+f"(c[0]), "+f"(c[1]), "+f"(c[2]), "+f"(c[3])
        : "r"(a[0]), "r"(a[1]), "r"(a[2]), "r"(a[3]), "r"(b[0]), "r"(b[1]));
}

__device__ __forceinline__ void stcs2(float* p, float2 v) {
    asm volatile("st.global.cs.v2.f32 [%0], {%1,%2};" :: "l"(p), "f"(v.x), "f"(v.y)
                 : "memory");
}

__device__ __forceinline__ void cpasync16(uint32_t dst, const void* src) {
    asm volatile("cp.async.cg.shared.global [%0], [%1], 16;" :: "r"(dst), "l"(src)
                 : "memory");
}

// SMEM: pitch-144 rows (conflict-free ldmatrix). A: 64 rows, B: 256 rows.
#define PITCHB 144
#define SM_AH  0
#define SM_AL  (TM * PITCHB)                 // 9216
#define SM_BH  (2 * TM * PITCHB)             // 18432
#define SM_BL  (2 * TM * PITCHB + TN * PITCHB)  // 55296
#define SM_TOTAL (2 * TM * PITCHB + 2 * TN * PITCHB)  // 92160

// ---------------------------------------------------------------------------
// Stage 2: out[s,i,j] = sum_d x1[s,i,d] * Q[s,j,d] via bf16x3 mma.sync.
// 64x256 tile/CTA (1KB-contiguous row chunks for DRAM page locality).
// 8 warps (2x4), warp tile 32x64, K=64 resident.
// ---------------------------------------------------------------------------
__global__ __launch_bounds__(256, 2) void gemm_mma(const float* __restrict__ bias,
                                                   float* __restrict__ out) {
    extern __shared__ char smem[];
    const uint32_t sb = smem_u32(smem);
    const int tid = threadIdx.x, wid = tid >> 5, lid = tid & 31;
    const int s = blockIdx.z, bj = blockIdx.x, bi = blockIdx.y;
    const int warp_m = wid >> 2;   // 0..1, 32 rows
    const int warp_n = wid & 3;    // 0..3, 64 cols

    // ---- Prologue: cp.async the 4 pre-split tiles ----
    const size_t Abase = ((size_t)s * NN + (size_t)bi * TM) * DD;
    const size_t Bbase = ((size_t)s * NN + (size_t)bj * TN) * DD;

    #pragma unroll
    for (int it = 0; it < 2; ++it) {            // A: 512 chunks per array
        int idx = it * 256 + tid;
        int row = idx >> 3, c = idx & 7;
        uint32_t so = (uint32_t)(row * PITCHB + c * 16);
        size_t go = (size_t)row * DD + c * 8;
        cpasync16(sb + SM_AH + so, g_Ah + Abase + go);
        cpasync16(sb + SM_AL + so, g_Al + Abase + go);
    }
    #pragma unroll
    for (int it = 0; it < 8; ++it) {            // B: 2048 chunks per array
        int idx = it * 256 + tid;
        int row = idx >> 3, c = idx & 7;
        uint32_t so = (uint32_t)(row * PITCHB + c * 16);
        size_t go = (size_t)row * DD + c * 8;
        cpasync16(sb + SM_BH + so, g_Bh + Bbase + go);
        cpasync16(sb + SM_BL + so, g_Bl + Bbase + go);
    }
    asm volatile("cp.async.commit_group;" ::: "memory");
    asm volatile("cp.async.wait_group 0;" ::: "memory");
    __syncthreads();

    // ---- Per-lane ldmatrix base addresses ----
    const uint32_t a_lane = (uint32_t)((warp_m * 32 + (lid & 15)) * PITCHB +
                                       ((lid >> 4) * 8) * 2);
    const uint32_t b_lane = (uint32_t)((warp_n * 64 + ((lid >> 4) & 1) * 8 + (lid & 7)) * PITCHB +
                                       (((lid >> 3) & 1) * 8) * 2);

    float acc[2][8][4];
    #pragma unroll
    for (int mt = 0; mt < 2; ++mt)
        #pragma unroll
        for (int nt = 0; nt < 8; ++nt)
            #pragma unroll
            for (int r = 0; r < 4; ++r) acc[mt][nt][r] = 0.f;

    const uint32_t pAh = sb + SM_AH + a_lane, pAl = sb + SM_AL + a_lane;
    const uint32_t pBh = sb + SM_BH + b_lane, pBl = sb + SM_BL + b_lane;

    // ---- Mainloop with fragment reuse: Ah*Bh, Al*Bh, Ah*Bl per k-step ----
    #pragma unroll
    for (int ks = 0; ks < 4; ++ks) {
        const uint32_t ko = (uint32_t)(ks * 32);
        uint32_t ah[2][4], al[2][4], bh[4][4], bl[4][4];
        #pragma unroll
        for (int mt = 0; mt < 2; ++mt)
            ldsm4(ah[mt], pAh + (uint32_t)(mt * 16 * PITCHB) + ko);
        #pragma unroll
        for (int nq = 0; nq < 4; ++nq)
            ldsm4(bh[nq], pBh + (uint32_t)(nq * 16 * PITCHB) + ko);
        #pragma unroll
        for (int mt = 0; mt < 2; ++mt)
            #pragma unroll
            for (int nq = 0; nq < 4; ++nq) {
                mma16816(acc[mt][2 * nq],     ah[mt], &bh[nq][0]);
                mma16816(acc[mt][2 * nq + 1], ah[mt], &bh[nq][2]);
            }
        #pragma unroll
        for (int mt = 0; mt < 2; ++mt)
            ldsm4(al[mt], pAl + (uint32_t)(mt * 16 * PITCHB) + ko);
        #pragma unroll
        for (int mt = 0; mt < 2; ++mt)
            #pragma unroll
            for (int nq = 0; nq < 4; ++nq) {
                mma16816(acc[mt][2 * nq],     al[mt], &bh[nq][0]);
                mma16816(acc[mt][2 * nq + 1], al[mt], &bh[nq][2]);
            }
        #pragma unroll
        for (int nq = 0; nq < 4; ++nq)
            ldsm4(bl[nq], pBl + (uint32_t)(nq * 16 * PITCHB) + ko);
        #pragma unroll
        for (int mt = 0; mt < 2; ++mt)
            #pragma unroll
            for (int nq = 0; nq < 4; ++nq) {
                mma16816(acc[mt][2 * nq],     ah[mt], &bl[nq][0]);
                mma16816(acc[mt][2 * nq + 1], ah[mt], &bl[nq][2]);
            }
    }

    // ---- Epilogue: direct register stores (streaming), both batch copies ----
    const float bv = *bias;
    const size_t BST = (size_t)SS * NN * NN;
    const size_t i_base = (size_t)bi * TM + warp_m * 32 + (lid >> 2);
    const size_t j_base = (size_t)bj * TN + warp_n * 64 + (lid & 3) * 2;

    #pragma unroll
    for (int mt = 0; mt < 2; ++mt) {
        #pragma unroll
        for (int nt = 0; nt < 8; ++nt) {
            float2 v0 = make_float2(acc[mt][nt][0] + bv, acc[mt][nt][1] + bv);
            float2 v1 = make_float2(acc[mt][nt][2] + bv, acc[mt][nt][3] + bv);
            float* d = out + ((size_t)s * NN + i_base + mt * 16) * NN + j_base + nt * 8;
            stcs2(d, v0);
            stcs2(d + 8 * NN, v1);
            stcs2(d + BST, v0);
            stcs2(d + BST + 8 * NN, v1);
        }
    }
}

// ---------------------------------------------------------------------------
// Launch
// ---------------------------------------------------------------------------
extern "C" void kernel_launch(void* const* d_in, const int* in_sizes, int n_in,
                              void* d_out, int out_size) {
    const float* x0   = (const float*)d_in[0];  // tensor0 (S,N,D)
    const float* x1   = (const float*)d_in[1];  // tensor1 (S,N,D)
    const float* W    = (const float*)d_in[2];  // kernel (D,D)
    const float* bias = (const float*)d_in[3];  // scalar
    float* out = (float*)d_out;                 // (2,S,N,N)

    prep_kernel<<<192, 256>>>(x0, x1, W);

    cudaFuncSetAttribute(gemm_mma, cudaFuncAttributeMaxDynamicSharedMemorySize, SM_TOTAL);
    dim3 grid(NN / TN, NN / TM, SS);
    gemm_mma<<<grid, 256, SM_TOTAL>>>(bias, out);
}

// round 8
// speedup vs baseline: 1.0666x; 1.0666x over previous
#include <cuda_runtime.h>
#include <cuda_bf16.h>
#include <cstdint>

#define SS 4
#define NN 4096
#define DD 64
#define TM 64     // i rows per CTA
#define TN 128    // j rows per CTA

// Pre-split bf16 hi/lo operand arrays (2 MB each, static — no allocs allowed)
__device__ __nv_bfloat16 g_Ah[(size_t)SS * NN * DD];
__device__ __nv_bfloat16 g_Al[(size_t)SS * NN * DD];
__device__ __nv_bfloat16 g_Bh[(size_t)SS * NN * DD];
__device__ __nv_bfloat16 g_Bl[(size_t)SS * NN * DD];

__device__ __forceinline__ uint32_t pkbf2(float a, float b) {
    __nv_bfloat162 t = __floats2bfloat162_rn(a, b);
    return *(uint32_t*)&t;
}

// ---------------------------------------------------------------------------
// Stage 1 (fused): blocks [0,128):  Q = x0 @ W^T, split -> g_Bh/g_Bl
//                  blocks [128,192): split x1 -> g_Ah/g_Al
// ---------------------------------------------------------------------------
__global__ __launch_bounds__(256) void prep_kernel(const float* __restrict__ x0,
                                                   const float* __restrict__ x1,
                                                   const float* __restrict__ W) {
    const int tid = threadIdx.x;
    if (blockIdx.x < 128) {
        __shared__ float Ws[DD * DD];
        #pragma unroll
        for (int i = tid; i < DD * DD / 4; i += 256)
            ((float4*)Ws)[i] = ((const float4*)W)[i];
        __syncthreads();

        int gid = blockIdx.x * 256 + tid;      // 0 .. 2*S*N-1
        int row = gid >> 1;
        int half = gid & 1;                    // 32 d-outputs

        const float4* xr = (const float4*)(x0 + (size_t)row * DD);
        float4 x[16];
        #pragma unroll
        for (int e = 0; e < 16; ++e) x[e] = xr[e];

        uint2* qh = (uint2*)(g_Bh + (size_t)row * DD + half * 32);
        uint2* ql = (uint2*)(g_Bl + (size_t)row * DD + half * 32);
        #pragma unroll
        for (int d4 = 0; d4 < 8; ++d4) {
            float r[4];
            #pragma unroll
            for (int dd = 0; dd < 4; ++dd) {
                int d = half * 32 + d4 * 4 + dd;
                const float4* wr = (const float4*)(Ws + d * DD);
                float a0 = 0.f, a1 = 0.f, a2 = 0.f, a3 = 0.f;
                #pragma unroll
                for (int e4 = 0; e4 < 16; e4 += 4) {
                    float4 w0 = wr[e4 + 0], w1 = wr[e4 + 1], w2 = wr[e4 + 2], w3 = wr[e4 + 3];
                    a0 += x[e4 + 0].x * w0.x + x[e4 + 0].y * w0.y + x[e4 + 0].z * w0.z + x[e4 + 0].w * w0.w;
                    a1 += x[e4 + 1].x * w1.x + x[e4 + 1].y * w1.y + x[e4 + 1].z * w1.z + x[e4 + 1].w * w1.w;
                    a2 += x[e4 + 2].x * w2.x + x[e4 + 2].y * w2.y + x[e4 + 2].z * w2.z + x[e4 + 2].w * w2.w;
                    a3 += x[e4 + 3].x * w3.x + x[e4 + 3].y * w3.y + x[e4 + 3].z * w3.z + x[e4 + 3].w * w3.w;
                }
                r[dd] = (a0 + a1) + (a2 + a3);
            }
            float h0 = __bfloat162float(__float2bfloat16(r[0]));
            float h1 = __bfloat162float(__float2bfloat16(r[1]));
            float h2 = __bfloat162float(__float2bfloat16(r[2]));
            float h3 = __bfloat162float(__float2bfloat16(r[3]));
            qh[d4] = make_uint2(pkbf2(h0, h1), pkbf2(h2, h3));
            ql[d4] = make_uint2(pkbf2(r[0] - h0, r[1] - h1), pkbf2(r[2] - h2, r[3] - h3));
        }
    } else {
        // x1 split: 64 blocks over 262144 float4
        int idx = (blockIdx.x - 128) * 256 + tid;
        const float4* src = (const float4*)x1;
        uint2* ah = (uint2*)g_Ah;
        uint2* al = (uint2*)g_Al;
        #pragma unroll
        for (int it = 0; it < 16; ++it) {
            int i = it * 16384 + idx;
            float4 v = src[i];
            float hx = __bfloat162float(__float2bfloat16(v.x));
            float hy = __bfloat162float(__float2bfloat16(v.y));
            float hz = __bfloat162float(__float2bfloat16(v.z));
            float hw = __bfloat162float(__float2bfloat16(v.w));
            ah[i] = make_uint2(pkbf2(hx, hy), pkbf2(hz, hw));
            al[i] = make_uint2(pkbf2(v.x - hx, v.y - hy), pkbf2(v.z - hz, v.w - hw));
        }
    }
}

// ---------------------------------------------------------------------------
// Baseline-PTX tensor core helpers
// ---------------------------------------------------------------------------
__device__ __forceinline__ uint32_t smem_u32(const void* p) {
    uint32_t a;
    asm("{ .reg .u64 t; cvta.to.shared.u64 t, %1; cvt.u32.u64 %0, t; }" : "=r"(a) : "l"(p));
    return a;
}

__device__ __forceinline__ void ldsm4(uint32_t* r, uint32_t addr) {
    asm volatile("ldmatrix.sync.aligned.m8n8.x4.shared.b16 {%0,%1,%2,%3}, [%4];"
                 : "=r"(r[0]), "=r"(r[1]), "=r"(r[2]), "=r"(r[3]) : "r"(addr));
}

__device__ __forceinline__ void mma16816(float* c, const uint32_t* a,
                                         const uint32_t* b) {
    asm volatile(
        "mma.sync.aligned.m16n8k16.row.col.f32.bf16.bf16.f32 "
        "{%0,%1,%2,%3}, {%4,%5,%6,%7}, {%8,%9}, {%0,%1,%2,%3};"
        : "+f"(c[0]), "+f"(c[1]), "+f"(c[2]), "+f"(c[3])
        : "r"(a[0]), "r"(a[1]), "r"(a[2]), "r"(a[3]), "r"(b[0]), "r"(b[1]));
}

__device__ __forceinline__ void stcs2(float* p, float2 v) {
    asm volatile("st.global.cs.v2.f32 [%0], {%1,%2};" :: "l"(p), "f"(v.x), "f"(v.y)
                 : "memory");
}

__device__ __forceinline__ void cpasync16(uint32_t dst, const void* src) {
    asm volatile("cp.async.cg.shared.global [%0], [%1], 16;" :: "r"(dst), "l"(src)
                 : "memory");
}

// SMEM: pitch-144 rows (conflict-free ldmatrix). A: 64 rows, B: 128 rows.
#define PITCHB 144
#define SM_AH  0
#define SM_AL  (TM * PITCHB)                        // 9216
#define SM_BH  (2 * TM * PITCHB)                    // 18432
#define SM_BL  (2 * TM * PITCHB + TN * PITCHB)      // 36864
#define SM_TOTAL (2 * TM * PITCHB + 2 * TN * PITCHB)  // 55296

// ---------------------------------------------------------------------------
// Stage 2: out[s,i,j] = sum_d x1[s,i,d] * Q[s,j,d] via bf16x3 mma.sync.
// 64x128 tile/CTA, 128 threads (4 warps, 2x2), warp tile 32x64, K=64 resident.
// Small CTA -> 4 CTAs/SM for cross-CTA phase overlap (epilogue vs mainloop).
// ---------------------------------------------------------------------------
__global__ __launch_bounds__(128, 4) void gemm_mma(const float* __restrict__ bias,
                                                   float* __restrict__ out) {
    extern __shared__ char smem[];
    const uint32_t sb = smem_u32(smem);
    const int tid = threadIdx.x, wid = tid >> 5, lid = tid & 31;
    const int s = blockIdx.z, bj = blockIdx.x, bi = blockIdx.y;
    const int warp_m = wid >> 1;   // 0..1, 32 rows
    const int warp_n = wid & 1;    // 0..1, 64 cols

    // ---- Prologue: cp.async the 4 pre-split tiles ----
    const size_t Abase = ((size_t)s * NN + (size_t)bi * TM) * DD;
    const size_t Bbase = ((size_t)s * NN + (size_t)bj * TN) * DD;

    #pragma unroll
    for (int it = 0; it < 4; ++it) {            // A: 512 chunks per array
        int idx = it * 128 + tid;
        int row = idx >> 3, c = idx & 7;
        uint32_t so = (uint32_t)(row * PITCHB + c * 16);
        size_t go = (size_t)row * DD + c * 8;
        cpasync16(sb + SM_AH + so, g_Ah + Abase + go);
        cpasync16(sb + SM_AL + so, g_Al + Abase + go);
    }
    #pragma unroll
    for (int it = 0; it < 8; ++it) {            // B: 1024 chunks per array
        int idx = it * 128 + tid;
        int row = idx >> 3, c = idx & 7;
        uint32_t so = (uint32_t)(row * PITCHB + c * 16);
        size_t go = (size_t)row * DD + c * 8;
        cpasync16(sb + SM_BH + so, g_Bh + Bbase + go);
        cpasync16(sb + SM_BL + so, g_Bl + Bbase + go);
    }
    asm volatile("cp.async.commit_group;" ::: "memory");
    asm volatile("cp.async.wait_group 0;" ::: "memory");
    __syncthreads();

    // ---- Per-lane ldmatrix base addresses ----
    const uint32_t a_lane = (uint32_t)((warp_m * 32 + (lid & 15)) * PITCHB +
                                       ((lid >> 4) * 8) * 2);
    const uint32_t b_lane = (uint32_t)((warp_n * 64 + ((lid >> 4) & 1) * 8 + (lid & 7)) * PITCHB +
                                       (((lid >> 3) & 1) * 8) * 2);

    float acc[2][8][4];
    #pragma unroll
    for (int mt = 0; mt < 2; ++mt)
        #pragma unroll
        for (int nt = 0; nt < 8; ++nt)
            #pragma unroll
            for (int r = 0; r < 4; ++r) acc[mt][nt][r] = 0.f;

    const uint32_t pAh = sb + SM_AH + a_lane, pAl = sb + SM_AL + a_lane;
    const uint32_t pBh = sb + SM_BH + b_lane, pBl = sb + SM_BL + b_lane;

    // ---- Mainloop with fragment reuse: Ah*Bh, Al*Bh, Ah*Bl per k-step ----
    #pragma unroll
    for (int ks = 0; ks < 4; ++ks) {
        const uint32_t ko = (uint32_t)(ks * 32);
        uint32_t ah[2][4], al[2][4], bh[4][4], bl[4][4];
        #pragma unroll
        for (int mt = 0; mt < 2; ++mt)
            ldsm4(ah[mt], pAh + (uint32_t)(mt * 16 * PITCHB) + ko);
        #pragma unroll
        for (int nq = 0; nq < 4; ++nq)
            ldsm4(bh[nq], pBh + (uint32_t)(nq * 16 * PITCHB) + ko);
        #pragma unroll
        for (int mt = 0; mt < 2; ++mt)
            #pragma unroll
            for (int nq = 0; nq < 4; ++nq) {
                mma16816(acc[mt][2 * nq],     ah[mt], &bh[nq][0]);
                mma16816(acc[mt][2 * nq + 1], ah[mt], &bh[nq][2]);
            }
        #pragma unroll
        for (int mt = 0; mt < 2; ++mt)
            ldsm4(al[mt], pAl + (uint32_t)(mt * 16 * PITCHB) + ko);
        #pragma unroll
        for (int mt = 0; mt < 2; ++mt)
            #pragma unroll
            for (int nq = 0; nq < 4; ++nq) {
                mma16816(acc[mt][2 * nq],     al[mt], &bh[nq][0]);
                mma16816(acc[mt][2 * nq + 1], al[mt], &bh[nq][2]);
            }
        #pragma unroll
        for (int nq = 0; nq < 4; ++nq)
            ldsm4(bl[nq], pBl + (uint32_t)(nq * 16 * PITCHB) + ko);
        #pragma unroll
        for (int mt = 0; mt < 2; ++mt)
            #pragma unroll
            for (int nq = 0; nq < 4; ++nq) {
                mma16816(acc[mt][2 * nq],     ah[mt], &bl[nq][0]);
                mma16816(acc[mt][2 * nq + 1], ah[mt], &bl[nq][2]);
            }
    }

    // ---- Epilogue: direct register stores (streaming), both batch copies ----
    const float bv = *bias;
    const size_t BST = (size_t)SS * NN * NN;
    const size_t i_base = (size_t)bi * TM + warp_m * 32 + (lid >> 2);
    const size_t j_base = (size_t)bj * TN + warp_n * 64 + (lid & 3) * 2;

    #pragma unroll
    for (int mt = 0; mt < 2; ++mt) {
        #pragma unroll
        for (int nt = 0; nt < 8; ++nt) {
            float2 v0 = make_float2(acc[mt][nt][0] + bv, acc[mt][nt][1] + bv);
            float2 v1 = make_float2(acc[mt][nt][2] + bv, acc[mt][nt][3] + bv);
            float* d = out + ((size_t)s * NN + i_base + mt * 16) * NN + j_base + nt * 8;
            stcs2(d, v0);
            stcs2(d + 8 * NN, v1);
            stcs2(d + BST, v0);
            stcs2(d + BST + 8 * NN, v1);
        }
    }
}

// ---------------------------------------------------------------------------
// Launch
// ---------------------------------------------------------------------------
extern "C" void kernel_launch(void* const* d_in, const int* in_sizes, int n_in,
                              void* d_out, int out_size) {
    const float* x0   = (const float*)d_in[0];  // tensor0 (S,N,D)
    const float* x1   = (const float*)d_in[1];  // tensor1 (S,N,D)
    const float* W    = (const float*)d_in[2];  // kernel (D,D)
    const float* bias = (const float*)d_in[3];  // scalar
    float* out = (float*)d_out;                 // (2,S,N,N)

    prep_kernel<<<192, 256>>>(x0, x1, W);

    cudaFuncSetAttribute(gemm_mma, cudaFuncAttributeMaxDynamicSharedMemorySize, SM_TOTAL);
    dim3 grid(NN / TN, NN / TM, SS);
    gemm_mma<<<grid, 128, SM_TOTAL>>>(bias, out);
}